// round 5
// baseline (speedup 1.0000x reference)
#include <cuda_runtime.h>
#include <cuda_fp16.h>
#include <math.h>

#define NN 100000
#define DD 64
#define EE 1600000
#define ETOT (EE + NN)
#define NB_SCAN 391   // ceil(NN/256)

// ---- scratch ----
__device__ __half g_h16[NN * DD];   // transformed features (payload, fp16)
__device__ float  g_x1[NN * DD];
__device__ float  g_x2[NN * DD];
__device__ float  g_es[NN];
__device__ float  g_ed[NN];
__device__ int    g_counts[NN];
__device__ int    g_rowptr[NN + 1];
__device__ int    g_cursor[NN];
__device__ int    g_csr[ETOT];
__device__ int    g_bsum[NB_SCAN];
__device__ unsigned g_gmaxu[3];

// monotone float <-> orderable uint
__device__ __forceinline__ unsigned fenc(float f) {
    unsigned b = __float_as_uint(f);
    return (b & 0x80000000u) ? ~b : (b | 0x80000000u);
}
__device__ __forceinline__ float fdec(unsigned e) {
    return __uint_as_float((e & 0x80000000u) ? (e ^ 0x80000000u) : ~e);
}

// ---- small init: counts = 1 (self loop), gmax reset ----
__global__ void k_initsmall() {
    int i = blockIdx.x * blockDim.x + threadIdx.x;
    if (i < NN) g_counts[i] = 1;
    if (i < 3) g_gmaxu[i] = 0u;
}

// ---- in-degree count (int4 loads) ----
__global__ void k_count(const int* __restrict__ dsts) {
    int i = blockIdx.x * blockDim.x + threadIdx.x;
    if (i >= EE / 4) return;
    int4 d = ((const int4*)dsts)[i];
    atomicAdd(&g_counts[d.x], 1);
    atomicAdd(&g_counts[d.y], 1);
    atomicAdd(&g_counts[d.z], 1);
    atomicAdd(&g_counts[d.w], 1);
}

// ---- block sums of counts ----
__global__ void __launch_bounds__(256) k_bsum() {
    __shared__ int sh[256];
    int t = threadIdx.x;
    int i = blockIdx.x * 256 + t;
    sh[t] = (i < NN) ? g_counts[i] : 0;
    __syncthreads();
    for (int o = 128; o > 0; o >>= 1) {
        if (t < o) sh[t] += sh[t + o];
        __syncthreads();
    }
    if (t == 0) g_bsum[blockIdx.x] = sh[0];
}

// ---- rowptr: per-block offset + local scan ----
__global__ void __launch_bounds__(256) k_fillptr() {
    __shared__ int sh[256];
    __shared__ int wsum[8];
    __shared__ int s_off;
    int t = threadIdx.x, b = blockIdx.x;
    int part = 0;
    for (int j = t; j < b; j += 256) part += g_bsum[j];
    sh[t] = part;
    __syncthreads();
    for (int o = 128; o > 0; o >>= 1) {
        if (t < o) sh[t] += sh[t + o];
        __syncthreads();
    }
    if (t == 0) s_off = sh[0];
    __syncthreads();

    int i = b * 256 + t;
    int c = (i < NN) ? g_counts[i] : 0;
    int lane = t & 31, w = t >> 5;
    int v = c;
#pragma unroll
    for (int o = 1; o < 32; o <<= 1) {
        int u = __shfl_up_sync(0xffffffffu, v, o);
        if (lane >= o) v += u;
    }
    if (lane == 31) wsum[w] = v;
    __syncthreads();
    if (t == 0) {
        int run = 0;
#pragma unroll
        for (int j = 0; j < 8; j++) { int tmp = wsum[j]; wsum[j] = run; run += tmp; }
    }
    __syncthreads();
    int excl = s_off + wsum[w] + v - c;
    if (i < NN) {
        g_rowptr[i] = excl;
        g_cursor[i] = excl;
        if (i == NN - 1) g_rowptr[NN] = excl + c;
    }
}

// ---- scatter src ids into dst buckets (int4 edges + self loops) ----
__global__ void k_fill(const int* __restrict__ srcs, const int* __restrict__ dsts) {
    int i = blockIdx.x * blockDim.x + threadIdx.x;
    if (i < EE / 4) {
        int4 s4 = ((const int4*)srcs)[i];
        int4 d4 = ((const int4*)dsts)[i];
        g_csr[atomicAdd(&g_cursor[d4.x], 1)] = s4.x;
        g_csr[atomicAdd(&g_cursor[d4.y], 1)] = s4.y;
        g_csr[atomicAdd(&g_cursor[d4.z], 1)] = s4.z;
        g_csr[atomicAdd(&g_cursor[d4.w], 1)] = s4.w;
    } else {
        int n = i - EE / 4;
        if (n < NN) g_csr[atomicAdd(&g_cursor[n], 1)] = n;
    }
}

// ---- transform: h = x@W (fp16 store); es/ed; fused block-max of es ----
__global__ void __launch_bounds__(256) k_transform(
    int layer, const float* __restrict__ emb,
    const float* __restrict__ W,
    const float* __restrict__ a_s, const float* __restrict__ a_d)
{
    __shared__ float Xs[64 * 64];
    __shared__ float Ws[64 * 64];
    __shared__ float ash[64];
    __shared__ float adh[64];
    __shared__ float smax[8];
    const float* x = (layer == 0) ? emb : (layer == 1 ? g_x1 : g_x2);
    int tid = threadIdx.x;
    int rb = blockIdx.x * 64;

    float4* Ws4 = (float4*)Ws;
    const float4* Wg4 = (const float4*)W;
#pragma unroll
    for (int j = tid; j < 1024; j += 256) Ws4[j] = Wg4[j];
    if (tid < 64) { ash[tid] = a_s[tid]; adh[tid] = a_d[tid]; }

    float4* Xs4 = (float4*)Xs;
    const float4* Xg4 = (const float4*)x;
    int nrows = NN - rb; if (nrows > 64) nrows = 64;
#pragma unroll
    for (int j = tid; j < 1024; j += 256) {
        int r = j >> 4;
        Xs4[j] = (r < nrows) ? Xg4[rb * 16 + j] : make_float4(0.f, 0.f, 0.f, 0.f);
    }
    __syncthreads();

    int tx = tid & 15, ty = tid >> 4;
    float4 acc[4];
#pragma unroll
    for (int i = 0; i < 4; i++) acc[i] = make_float4(0.f, 0.f, 0.f, 0.f);

#pragma unroll
    for (int k4 = 0; k4 < 16; k4++) {
        float4 wv0 = Ws4[(4 * k4 + 0) * 16 + tx];
        float4 wv1 = Ws4[(4 * k4 + 1) * 16 + tx];
        float4 wv2 = Ws4[(4 * k4 + 2) * 16 + tx];
        float4 wv3 = Ws4[(4 * k4 + 3) * 16 + tx];
#pragma unroll
        for (int i = 0; i < 4; i++) {
            float4 xv = Xs4[(ty * 4 + i) * 16 + k4];
            acc[i].x = fmaf(xv.x, wv0.x, acc[i].x);
            acc[i].y = fmaf(xv.x, wv0.y, acc[i].y);
            acc[i].z = fmaf(xv.x, wv0.z, acc[i].z);
            acc[i].w = fmaf(xv.x, wv0.w, acc[i].w);
            acc[i].x = fmaf(xv.y, wv1.x, acc[i].x);
            acc[i].y = fmaf(xv.y, wv1.y, acc[i].y);
            acc[i].z = fmaf(xv.y, wv1.z, acc[i].z);
            acc[i].w = fmaf(xv.y, wv1.w, acc[i].w);
            acc[i].x = fmaf(xv.z, wv2.x, acc[i].x);
            acc[i].y = fmaf(xv.z, wv2.y, acc[i].y);
            acc[i].z = fmaf(xv.z, wv2.z, acc[i].z);
            acc[i].w = fmaf(xv.z, wv2.w, acc[i].w);
            acc[i].x = fmaf(xv.w, wv3.x, acc[i].x);
            acc[i].y = fmaf(xv.w, wv3.y, acc[i].y);
            acc[i].z = fmaf(xv.w, wv3.z, acc[i].z);
            acc[i].w = fmaf(xv.w, wv3.w, acc[i].w);
        }
    }

    // store h as fp16 (uint2 = 4 elems), coalesced
    uint2* Hg = (uint2*)g_h16;
#pragma unroll
    for (int i = 0; i < 4; i++) {
        int r = ty * 4 + i;
        if (r < nrows) {
            __half2 lo = __float22half2_rn(make_float2(acc[i].x, acc[i].y));
            __half2 hi = __float22half2_rn(make_float2(acc[i].z, acc[i].w));
            Hg[(rb + r) * 16 + tx] = make_uint2(*(unsigned*)&lo, *(unsigned*)&hi);
        }
    }

    // es/ed partial dots + block max of es
    float4 as4 = ((const float4*)ash)[tx];
    float4 ad4 = ((const float4*)adh)[tx];
    float mmax = -3.4e38f;
#pragma unroll
    for (int i = 0; i < 4; i++) {
        float ps = acc[i].x * as4.x + acc[i].y * as4.y + acc[i].z * as4.z + acc[i].w * as4.w;
        float pd = acc[i].x * ad4.x + acc[i].y * ad4.y + acc[i].z * ad4.z + acc[i].w * ad4.w;
#pragma unroll
        for (int o = 8; o > 0; o >>= 1) {
            ps += __shfl_xor_sync(0xffffffffu, ps, o);
            pd += __shfl_xor_sync(0xffffffffu, pd, o);
        }
        int r = ty * 4 + i;
        if (tx == 0 && r < nrows) { g_es[rb + r] = ps; g_ed[rb + r] = pd; }
        if (r < nrows) mmax = fmaxf(mmax, ps);
    }
#pragma unroll
    for (int o = 16; o > 0; o >>= 1) mmax = fmaxf(mmax, __shfl_xor_sync(0xffffffffu, mmax, o));
    if ((tid & 31) == 0) smax[tid >> 5] = mmax;
    __syncthreads();
    if (tid == 0) {
        float bm = smax[0];
#pragma unroll
        for (int j = 1; j < 8; j++) bm = fmaxf(bm, smax[j]);
        atomicMax(&g_gmaxu[layer], fenc(bm));
    }
}

// ---- aggregate: warp per node, 4x 8-lane edge groups, fused final mean ----
__global__ void __launch_bounds__(256) k_agg(
    int layer, const float* __restrict__ bias,
    const float4* __restrict__ emb4, float4* __restrict__ out4)
{
    __shared__ float sbias[64];
    __shared__ float s_gmax;
    int tid = threadIdx.x;
    if (tid < 64) sbias[tid] = bias[tid];
    if (tid == 0) s_gmax = fdec(g_gmaxu[layer]);
    __syncthreads();

    int lane = tid & 31;
    int n = blockIdx.x * 8 + (tid >> 5);
    if (n >= NN) return;

    int beg = g_rowptr[n];
    int end = g_rowptr[n + 1];
    float edn = g_ed[n];
    float gm = s_gmax + edn;
    float m = (gm > 0.f) ? gm : 0.2f * gm;   // lrelu monotone => >= segment max

    int grp = lane >> 3, hl = lane & 7;      // 4 groups of 8 lanes, 1 edge/group
    float denom = 0.f;
    float acc[8];
#pragma unroll
    for (int j = 0; j < 8; j++) acc[j] = 0.f;
    const uint4* h4 = (const uint4*)g_h16;   // 8 fp16 per lane -> 128B/edge

#pragma unroll 2
    for (int k = beg + grp; k < end; k += 4) {
        int s = __ldg(&g_csr[k]);
        float e = __ldg(&g_es[s]) + edn;
        e = (e > 0.f) ? e : 0.2f * e;
        float w = __expf(e - m);
        denom += w;
        uint4 hv = h4[s * 8 + hl];
        float2 f0 = __half22float2(*(__half2*)&hv.x);
        float2 f1 = __half22float2(*(__half2*)&hv.y);
        float2 f2 = __half22float2(*(__half2*)&hv.z);
        float2 f3 = __half22float2(*(__half2*)&hv.w);
        acc[0] = fmaf(w, f0.x, acc[0]);
        acc[1] = fmaf(w, f0.y, acc[1]);
        acc[2] = fmaf(w, f1.x, acc[2]);
        acc[3] = fmaf(w, f1.y, acc[3]);
        acc[4] = fmaf(w, f2.x, acc[4]);
        acc[5] = fmaf(w, f2.y, acc[5]);
        acc[6] = fmaf(w, f3.x, acc[6]);
        acc[7] = fmaf(w, f3.y, acc[7]);
    }
    // combine the 4 groups (lanes hl, hl+8, hl+16, hl+24)
    denom += __shfl_xor_sync(0xffffffffu, denom, 8);
    denom += __shfl_xor_sync(0xffffffffu, denom, 16);
#pragma unroll
    for (int j = 0; j < 8; j++) {
        acc[j] += __shfl_xor_sync(0xffffffffu, acc[j], 8);
        acc[j] += __shfl_xor_sync(0xffffffffu, acc[j], 16);
    }

    if (grp == 0) {
        float inv = 1.f / (denom + 1e-16f);
        float v[8];
#pragma unroll
        for (int j = 0; j < 8; j++) {
            float t = acc[j] * inv + sbias[hl * 8 + j];
            v[j] = (t > 0.f) ? t : expm1f(t);   // ELU
        }
        if (layer == 2) {
            // out = (emb + x1 + x2 + x3) / 4
            const float4* x1_4 = (const float4*)g_x1;
            const float4* x2_4 = (const float4*)g_x2;
            int base = n * 16 + hl * 2;
#pragma unroll
            for (int p = 0; p < 2; p++) {
                float4 e4 = emb4[base + p];
                float4 a4 = x1_4[base + p];
                float4 b4 = x2_4[base + p];
                float4 o4;
                o4.x = (e4.x + a4.x + b4.x + v[p * 4 + 0]) * 0.25f;
                o4.y = (e4.y + a4.y + b4.y + v[p * 4 + 1]) * 0.25f;
                o4.z = (e4.z + a4.z + b4.z + v[p * 4 + 2]) * 0.25f;
                o4.w = (e4.w + a4.w + b4.w + v[p * 4 + 3]) * 0.25f;
                out4[base + p] = o4;
            }
        } else {
            float4* xo = (float4*)((layer == 0) ? g_x1 : g_x2);
            int base = n * 16 + hl * 2;
            xo[base]     = make_float4(v[0], v[1], v[2], v[3]);
            xo[base + 1] = make_float4(v[4], v[5], v[6], v[7]);
        }
    }
}

extern "C" void kernel_launch(void* const* d_in, const int* in_sizes, int n_in,
                              void* d_out, int out_size) {
    const int*   ei   = (const int*)d_in[0];
    const float* emb  = (const float*)d_in[1];
    const float* W    = (const float*)d_in[2];
    const float* a_s  = (const float*)d_in[3];
    const float* a_d  = (const float*)d_in[4];
    const float* bias = (const float*)d_in[5];
    float* out = (float*)d_out;

    const int* srcs = ei;
    const int* dsts = ei + EE;

    k_initsmall<<<(NN + 255) / 256, 256>>>();
    k_count<<<(EE / 4 + 255) / 256, 256>>>(dsts);
    k_bsum<<<NB_SCAN, 256>>>();
    // transform(l0) has no CSR dependency; placed 4th so ncu profiles it
    k_transform<<<(NN + 63) / 64, 256>>>(0, emb, W, a_s, a_d);
    k_fillptr<<<NB_SCAN, 256>>>();
    k_fill<<<(EE / 4 + NN + 255) / 256, 256>>>(srcs, dsts);
    k_agg<<<(NN + 7) / 8, 256>>>(0, bias, (const float4*)emb, (float4*)out);

    for (int l = 1; l < 3; l++) {
        k_transform<<<(NN + 63) / 64, 256>>>(l, emb, W + l * DD * DD,
                                             a_s + l * DD, a_d + l * DD);
        k_agg<<<(NN + 7) / 8, 256>>>(l, bias + l * DD, (const float4*)emb, (float4*)out);
    }
}

// round 6
// speedup vs baseline: 1.1952x; 1.1952x over previous
#include <cuda_runtime.h>
#include <cuda_fp16.h>
#include <math.h>

#define NN 100000
#define DD 64
#define EE 1600000
#define ETOT (EE + NN)
#define NB_SCAN 391   // ceil(NN/256)

// ---- scratch ----
__device__ __half g_h16[NN * DD];   // transformed features (payload, fp16)
__device__ float  g_x1[NN * DD];
__device__ float  g_x2[NN * DD];
__device__ float  g_es[NN];
__device__ float  g_ed[NN];
__device__ int    g_counts[NN];
__device__ int    g_rowptr[NN + 1];
__device__ int    g_cursor[NN];
__device__ int    g_csr[ETOT];
__device__ int    g_bsum[NB_SCAN];
__device__ unsigned g_gmaxu[3];

// monotone float <-> orderable uint
__device__ __forceinline__ unsigned fenc(float f) {
    unsigned b = __float_as_uint(f);
    return (b & 0x80000000u) ? ~b : (b | 0x80000000u);
}
__device__ __forceinline__ float fdec(unsigned e) {
    return __uint_as_float((e & 0x80000000u) ? (e ^ 0x80000000u) : ~e);
}

// ---- small init: counts = 1 (self loop), gmax reset ----
__global__ void k_initsmall() {
    int i = blockIdx.x * blockDim.x + threadIdx.x;
    if (i < NN) g_counts[i] = 1;
    if (i < 3) g_gmaxu[i] = 0u;
}

// ---- in-degree count (int4 loads) ----
__global__ void k_count(const int* __restrict__ dsts) {
    int i = blockIdx.x * blockDim.x + threadIdx.x;
    if (i >= EE / 4) return;
    int4 d = ((const int4*)dsts)[i];
    atomicAdd(&g_counts[d.x], 1);
    atomicAdd(&g_counts[d.y], 1);
    atomicAdd(&g_counts[d.z], 1);
    atomicAdd(&g_counts[d.w], 1);
}

// ---- block sums of counts ----
__global__ void __launch_bounds__(256) k_bsum() {
    __shared__ int sh[256];
    int t = threadIdx.x;
    int i = blockIdx.x * 256 + t;
    sh[t] = (i < NN) ? g_counts[i] : 0;
    __syncthreads();
    for (int o = 128; o > 0; o >>= 1) {
        if (t < o) sh[t] += sh[t + o];
        __syncthreads();
    }
    if (t == 0) g_bsum[blockIdx.x] = sh[0];
}

// ---- rowptr: per-block offset + local scan ----
__global__ void __launch_bounds__(256) k_fillptr() {
    __shared__ int sh[256];
    __shared__ int wsum[8];
    __shared__ int s_off;
    int t = threadIdx.x, b = blockIdx.x;
    int part = 0;
    for (int j = t; j < b; j += 256) part += g_bsum[j];
    sh[t] = part;
    __syncthreads();
    for (int o = 128; o > 0; o >>= 1) {
        if (t < o) sh[t] += sh[t + o];
        __syncthreads();
    }
    if (t == 0) s_off = sh[0];
    __syncthreads();

    int i = b * 256 + t;
    int c = (i < NN) ? g_counts[i] : 0;
    int lane = t & 31, w = t >> 5;
    int v = c;
#pragma unroll
    for (int o = 1; o < 32; o <<= 1) {
        int u = __shfl_up_sync(0xffffffffu, v, o);
        if (lane >= o) v += u;
    }
    if (lane == 31) wsum[w] = v;
    __syncthreads();
    if (t == 0) {
        int run = 0;
#pragma unroll
        for (int j = 0; j < 8; j++) { int tmp = wsum[j]; wsum[j] = run; run += tmp; }
    }
    __syncthreads();
    int excl = s_off + wsum[w] + v - c;
    if (i < NN) {
        g_rowptr[i] = excl;
        g_cursor[i] = excl;
        if (i == NN - 1) g_rowptr[NN] = excl + c;
    }
}

// ---- scatter src ids into dst buckets (+ self loops), scalar ----
__global__ void k_fill(const int* __restrict__ srcs, const int* __restrict__ dsts) {
    int i = blockIdx.x * blockDim.x + threadIdx.x;
    if (i >= ETOT) return;
    int s, d;
    if (i < EE) { s = srcs[i]; d = dsts[i]; }
    else        { s = d = i - EE; }
    int pos = atomicAdd(&g_cursor[d], 1);
    g_csr[pos] = s;
}

// ---- HMMA helper: m16n8k16 row.col f32.f16.f16.f32 ----
__device__ __forceinline__ void mma16816(
    float& c0, float& c1, float& c2, float& c3,
    unsigned a0, unsigned a1, unsigned a2, unsigned a3,
    unsigned b0, unsigned b1)
{
    asm volatile(
        "mma.sync.aligned.m16n8k16.row.col.f32.f16.f16.f32 "
        "{%0,%1,%2,%3}, {%4,%5,%6,%7}, {%8,%9}, {%0,%1,%2,%3};"
        : "+f"(c0), "+f"(c1), "+f"(c2), "+f"(c3)
        : "r"(a0), "r"(a1), "r"(a2), "r"(a3), "r"(b0), "r"(b1));
}

// ---- transform: h = x@W via HMMA; es/ed; fused block-max ----
// 128-row tile per block; 8 warps x (16 rows x 64 cols); fp16 in, fp32 accum
#define XPAD 72
__global__ void __launch_bounds__(256) k_transform(
    int layer, const float* __restrict__ emb,
    const float* __restrict__ W,
    const float* __restrict__ a_s, const float* __restrict__ a_d)
{
    __shared__ __half Xh[128][XPAD];
    __shared__ __half Wn[64][XPAD];   // Wn[n][k] = W[k][n] (transposed)
    __shared__ float ash[64];
    __shared__ float adh[64];
    __shared__ float smax[8];
    const float* x = (layer == 0) ? emb : (layer == 1 ? g_x1 : g_x2);
    int tid = threadIdx.x;
    int rb = blockIdx.x * 128;

    // W transpose-load: W row-major [k][n] -> Wn[n][k], fp16
    const float4* Wg4 = (const float4*)W;
#pragma unroll
    for (int idx = tid; idx < 1024; idx += 256) {
        int k = idx >> 4, n4 = (idx & 15) << 2;
        float4 w = Wg4[idx];
        Wn[n4 + 0][k] = __float2half(w.x);
        Wn[n4 + 1][k] = __float2half(w.y);
        Wn[n4 + 2][k] = __float2half(w.z);
        Wn[n4 + 3][k] = __float2half(w.w);
    }
    if (tid < 64) { ash[tid] = a_s[tid]; adh[tid] = a_d[tid]; }

    // X load: 128 rows x 64 cols fp32 -> fp16 smem
    const float4* Xg4 = (const float4*)x;
#pragma unroll
    for (int idx = tid; idx < 2048; idx += 256) {
        int r = idx >> 4, c4 = (idx & 15) << 2;
        float4 v = (rb + r < NN) ? Xg4[(rb + r) * 16 + (idx & 15)]
                                 : make_float4(0.f, 0.f, 0.f, 0.f);
        __half2* dst = (__half2*)&Xh[r][c4];
        dst[0] = __float22half2_rn(make_float2(v.x, v.y));
        dst[1] = __float22half2_rn(make_float2(v.z, v.w));
    }
    __syncthreads();

    int warp = tid >> 5, lane = tid & 31;
    int gid = lane >> 2, tig = lane & 3;
    int lrow = warp * 16 + gid;          // local row for c0/c1 (lrow+8 for c2/c3)

    float acc[8][4];
#pragma unroll
    for (int nt = 0; nt < 8; nt++)
#pragma unroll
        for (int j = 0; j < 4; j++) acc[nt][j] = 0.f;

#pragma unroll
    for (int ks = 0; ks < 4; ks++) {
        int kb = ks * 16;
        unsigned a0 = *(const unsigned*)&Xh[lrow][kb + 2 * tig];
        unsigned a1 = *(const unsigned*)&Xh[lrow + 8][kb + 2 * tig];
        unsigned a2 = *(const unsigned*)&Xh[lrow][kb + 2 * tig + 8];
        unsigned a3 = *(const unsigned*)&Xh[lrow + 8][kb + 2 * tig + 8];
#pragma unroll
        for (int nt = 0; nt < 8; nt++) {
            unsigned b0 = *(const unsigned*)&Wn[nt * 8 + gid][kb + 2 * tig];
            unsigned b1 = *(const unsigned*)&Wn[nt * 8 + gid][kb + 2 * tig + 8];
            mma16816(acc[nt][0], acc[nt][1], acc[nt][2], acc[nt][3],
                     a0, a1, a2, a3, b0, b1);
        }
    }

    // store h fp16 + es/ed partial dots
    int grow0 = rb + lrow;        // rows gid, gid+8 of this warp's 16-row slab
    int grow8 = grow0 + 8;
    float ps0 = 0.f, pd0 = 0.f, ps8 = 0.f, pd8 = 0.f;
#pragma unroll
    for (int nt = 0; nt < 8; nt++) {
        int col = nt * 8 + 2 * tig;
        if (grow0 < NN)
            *(__half2*)&g_h16[grow0 * 64 + col] =
                __float22half2_rn(make_float2(acc[nt][0], acc[nt][1]));
        if (grow8 < NN)
            *(__half2*)&g_h16[grow8 * 64 + col] =
                __float22half2_rn(make_float2(acc[nt][2], acc[nt][3]));
        float s0 = ash[col], s1 = ash[col + 1];
        float d0 = adh[col], d1 = adh[col + 1];
        ps0 += acc[nt][0] * s0 + acc[nt][1] * s1;
        pd0 += acc[nt][0] * d0 + acc[nt][1] * d1;
        ps8 += acc[nt][2] * s0 + acc[nt][3] * s1;
        pd8 += acc[nt][2] * d0 + acc[nt][3] * d1;
    }
    // reduce over the 4 tig lanes (same gid)
    ps0 += __shfl_xor_sync(0xffffffffu, ps0, 1);
    ps0 += __shfl_xor_sync(0xffffffffu, ps0, 2);
    pd0 += __shfl_xor_sync(0xffffffffu, pd0, 1);
    pd0 += __shfl_xor_sync(0xffffffffu, pd0, 2);
    ps8 += __shfl_xor_sync(0xffffffffu, ps8, 1);
    ps8 += __shfl_xor_sync(0xffffffffu, ps8, 2);
    pd8 += __shfl_xor_sync(0xffffffffu, pd8, 1);
    pd8 += __shfl_xor_sync(0xffffffffu, pd8, 2);
    if (tig == 0) {
        if (grow0 < NN) { g_es[grow0] = ps0; g_ed[grow0] = pd0; }
        if (grow8 < NN) { g_es[grow8] = ps8; g_ed[grow8] = pd8; }
    }

    // block max of es (all lanes hold reduced values)
    float mmax = -3.4e38f;
    if (grow0 < NN) mmax = fmaxf(mmax, ps0);
    if (grow8 < NN) mmax = fmaxf(mmax, ps8);
#pragma unroll
    for (int o = 16; o > 0; o >>= 1)
        mmax = fmaxf(mmax, __shfl_xor_sync(0xffffffffu, mmax, o));
    if (lane == 0) smax[warp] = mmax;
    __syncthreads();
    if (tid == 0) {
        float bm = smax[0];
#pragma unroll
        for (int j = 1; j < 8; j++) bm = fmaxf(bm, smax[j]);
        atomicMax(&g_gmaxu[layer], fenc(bm));
    }
}

// ---- aggregate: warp per node, 2 half-warps (R4 config), fused final mean ----
__global__ void __launch_bounds__(256) k_agg(
    int layer, const float* __restrict__ bias,
    const float4* __restrict__ emb4, float4* __restrict__ out4)
{
    __shared__ float sbias[64];
    __shared__ float s_gmax;
    int tid = threadIdx.x;
    if (tid < 64) sbias[tid] = bias[tid];
    if (tid == 0) s_gmax = fdec(g_gmaxu[layer]);
    __syncthreads();

    int lane = tid & 31;
    int n = blockIdx.x * 8 + (tid >> 5);
    if (n >= NN) return;

    int beg = g_rowptr[n];
    int end = g_rowptr[n + 1];
    float edn = g_ed[n];
    float gm = s_gmax + edn;
    float m = (gm > 0.f) ? gm : 0.2f * gm;   // lrelu monotone => >= segment max

    int half = lane >> 4, hl = lane & 15;
    float denom = 0.f;
    float4 acc = make_float4(0.f, 0.f, 0.f, 0.f);
    const uint2* h2 = (const uint2*)g_h16;

#pragma unroll 4
    for (int k = beg + half; k < end; k += 2) {
        int s = __ldg(&g_csr[k]);
        float e = __ldg(&g_es[s]) + edn;
        e = (e > 0.f) ? e : 0.2f * e;
        float w = __expf(e - m);
        denom += w;
        uint2 hv = h2[s * 16 + hl];          // 4 fp16 elems, 128B/half-warp
        float2 lo = __half22float2(*(__half2*)&hv.x);
        float2 hi = __half22float2(*(__half2*)&hv.y);
        acc.x = fmaf(w, lo.x, acc.x);
        acc.y = fmaf(w, lo.y, acc.y);
        acc.z = fmaf(w, hi.x, acc.z);
        acc.w = fmaf(w, hi.y, acc.w);
    }
    denom += __shfl_xor_sync(0xffffffffu, denom, 16);
    acc.x += __shfl_xor_sync(0xffffffffu, acc.x, 16);
    acc.y += __shfl_xor_sync(0xffffffffu, acc.y, 16);
    acc.z += __shfl_xor_sync(0xffffffffu, acc.z, 16);
    acc.w += __shfl_xor_sync(0xffffffffu, acc.w, 16);

    if (half == 0) {
        float inv = 1.f / (denom + 1e-16f);
        float4 b4 = ((const float4*)sbias)[hl];
        float4 v;
        v.x = acc.x * inv + b4.x;
        v.y = acc.y * inv + b4.y;
        v.z = acc.z * inv + b4.z;
        v.w = acc.w * inv + b4.w;
        v.x = (v.x > 0.f) ? v.x : expm1f(v.x);
        v.y = (v.y > 0.f) ? v.y : expm1f(v.y);
        v.z = (v.z > 0.f) ? v.z : expm1f(v.z);
        v.w = (v.w > 0.f) ? v.w : expm1f(v.w);

        int base = n * 16 + hl;
        if (layer == 2) {
            // out = (emb + x1 + x2 + x3) / 4
            float4 e4 = emb4[base];
            float4 a4 = ((const float4*)g_x1)[base];
            float4 c4 = ((const float4*)g_x2)[base];
            float4 o4;
            o4.x = (e4.x + a4.x + c4.x + v.x) * 0.25f;
            o4.y = (e4.y + a4.y + c4.y + v.y) * 0.25f;
            o4.z = (e4.z + a4.z + c4.z + v.z) * 0.25f;
            o4.w = (e4.w + a4.w + c4.w + v.w) * 0.25f;
            out4[base] = o4;
        } else {
            float4* xo = (float4*)((layer == 0) ? g_x1 : g_x2);
            xo[base] = v;
        }
    }
}

extern "C" void kernel_launch(void* const* d_in, const int* in_sizes, int n_in,
                              void* d_out, int out_size) {
    const int*   ei   = (const int*)d_in[0];
    const float* emb  = (const float*)d_in[1];
    const float* W    = (const float*)d_in[2];
    const float* a_s  = (const float*)d_in[3];
    const float* a_d  = (const float*)d_in[4];
    const float* bias = (const float*)d_in[5];
    float* out = (float*)d_out;

    const int* srcs = ei;
    const int* dsts = ei + EE;

    k_initsmall<<<(NN + 255) / 256, 256>>>();
    k_count<<<(EE / 4 + 255) / 256, 256>>>(dsts);
    k_bsum<<<NB_SCAN, 256>>>();
    // transform(l0) has no CSR dependency; placed 4th so ncu profiles it
    k_transform<<<(NN + 127) / 128, 256>>>(0, emb, W, a_s, a_d);
    k_fillptr<<<NB_SCAN, 256>>>();
    k_fill<<<(ETOT + 255) / 256, 256>>>(srcs, dsts);
    k_agg<<<(NN + 7) / 8, 256>>>(0, bias, (const float4*)emb, (float4*)out);

    for (int l = 1; l < 3; l++) {
        k_transform<<<(NN + 127) / 128, 256>>>(l, emb, W + l * DD * DD,
                                               a_s + l * DD, a_d + l * DD);
        k_agg<<<(NN + 7) / 8, 256>>>(l, bias + l * DD, (const float4*)emb, (float4*)out);
    }
}

// round 7
// speedup vs baseline: 1.2034x; 1.0068x over previous
#include <cuda_runtime.h>
#include <cuda_fp16.h>
#include <math.h>

#define NN 100000
#define DD 64
#define EE 1600000
#define ETOT (EE + NN)
#define NB_SCAN 391   // ceil(NN/256)

// ---- scratch ----
__device__ __half g_h16[NN * DD];   // transformed features (payload, fp16)
__device__ float  g_x1[NN * DD];
__device__ float  g_x2[NN * DD];
__device__ float  g_es[NN];
__device__ float  g_ed[NN];
__device__ float  g_w[ETOT];        // per-edge softmax numerator
__device__ int    g_counts[NN];
__device__ int    g_rowptr[NN + 1];
__device__ int    g_cursor[NN];
__device__ int2   g_csrd[ETOT];     // (src, dst) per CSR slot
__device__ int    g_bsum[NB_SCAN];
__device__ unsigned g_gmaxu[3];

// monotone float <-> orderable uint
__device__ __forceinline__ unsigned fenc(float f) {
    unsigned b = __float_as_uint(f);
    return (b & 0x80000000u) ? ~b : (b | 0x80000000u);
}
__device__ __forceinline__ float fdec(unsigned e) {
    return __uint_as_float((e & 0x80000000u) ? (e ^ 0x80000000u) : ~e);
}
__device__ __forceinline__ unsigned sptr(const void* p) {
    return (unsigned)__cvta_generic_to_shared(p);
}

// ---- small init ----
__global__ void k_initsmall() {
    int i = blockIdx.x * blockDim.x + threadIdx.x;
    if (i < NN) g_counts[i] = 1;
    if (i < 3) g_gmaxu[i] = 0u;
}

// ---- in-degree count ----
__global__ void k_count(const int* __restrict__ dsts) {
    int i = blockIdx.x * blockDim.x + threadIdx.x;
    if (i >= EE / 4) return;
    int4 d = ((const int4*)dsts)[i];
    atomicAdd(&g_counts[d.x], 1);
    atomicAdd(&g_counts[d.y], 1);
    atomicAdd(&g_counts[d.z], 1);
    atomicAdd(&g_counts[d.w], 1);
}

// ---- block sums of counts ----
__global__ void __launch_bounds__(256) k_bsum() {
    __shared__ int sh[256];
    int t = threadIdx.x;
    int i = blockIdx.x * 256 + t;
    sh[t] = (i < NN) ? g_counts[i] : 0;
    __syncthreads();
    for (int o = 128; o > 0; o >>= 1) {
        if (t < o) sh[t] += sh[t + o];
        __syncthreads();
    }
    if (t == 0) g_bsum[blockIdx.x] = sh[0];
}

// ---- rowptr: per-block offset + local scan ----
__global__ void __launch_bounds__(256) k_fillptr() {
    __shared__ int sh[256];
    __shared__ int wsum[8];
    __shared__ int s_off;
    int t = threadIdx.x, b = blockIdx.x;
    int part = 0;
    for (int j = t; j < b; j += 256) part += g_bsum[j];
    sh[t] = part;
    __syncthreads();
    for (int o = 128; o > 0; o >>= 1) {
        if (t < o) sh[t] += sh[t + o];
        __syncthreads();
    }
    if (t == 0) s_off = sh[0];
    __syncthreads();

    int i = b * 256 + t;
    int c = (i < NN) ? g_counts[i] : 0;
    int lane = t & 31, w = t >> 5;
    int v = c;
#pragma unroll
    for (int o = 1; o < 32; o <<= 1) {
        int u = __shfl_up_sync(0xffffffffu, v, o);
        if (lane >= o) v += u;
    }
    if (lane == 31) wsum[w] = v;
    __syncthreads();
    if (t == 0) {
        int run = 0;
#pragma unroll
        for (int j = 0; j < 8; j++) { int tmp = wsum[j]; wsum[j] = run; run += tmp; }
    }
    __syncthreads();
    int excl = s_off + wsum[w] + v - c;
    if (i < NN) {
        g_rowptr[i] = excl;
        g_cursor[i] = excl;
        if (i == NN - 1) g_rowptr[NN] = excl + c;
    }
}

// ---- scatter (src,dst) into dst buckets (+ self loops) ----
__global__ void k_fill(const int* __restrict__ srcs, const int* __restrict__ dsts) {
    int i = blockIdx.x * blockDim.x + threadIdx.x;
    if (i >= ETOT) return;
    int s, d;
    if (i < EE) { s = srcs[i]; d = dsts[i]; }
    else        { s = d = i - EE; }
    int pos = atomicAdd(&g_cursor[d], 1);
    g_csrd[pos] = make_int2(s, d);
}

// ---- HMMA helper ----
__device__ __forceinline__ void mma16816(
    float& c0, float& c1, float& c2, float& c3,
    unsigned a0, unsigned a1, unsigned a2, unsigned a3,
    unsigned b0, unsigned b1)
{
    asm volatile(
        "mma.sync.aligned.m16n8k16.row.col.f32.f16.f16.f32 "
        "{%0,%1,%2,%3}, {%4,%5,%6,%7}, {%8,%9}, {%0,%1,%2,%3};"
        : "+f"(c0), "+f"(c1), "+f"(c2), "+f"(c3)
        : "r"(a0), "r"(a1), "r"(a2), "r"(a3), "r"(b0), "r"(b1));
}
__device__ __forceinline__ void ldsm4(
    unsigned& r0, unsigned& r1, unsigned& r2, unsigned& r3, unsigned addr)
{
    asm volatile(
        "ldmatrix.sync.aligned.m8n8.x4.shared.b16 {%0,%1,%2,%3}, [%4];"
        : "=r"(r0), "=r"(r1), "=r"(r2), "=r"(r3) : "r"(addr));
}

// ---- transform: h = x@W via HMMA + ldmatrix; es/ed; fused block-max ----
#define XPAD 72
__global__ void __launch_bounds__(256) k_transform(
    int layer, const float* __restrict__ emb,
    const float* __restrict__ W,
    const float* __restrict__ a_s, const float* __restrict__ a_d)
{
    __shared__ __half Xh[128][XPAD];
    __shared__ __half Wn[64][XPAD];   // Wn[n][k] = W[k][n]
    __shared__ float ash[64];
    __shared__ float adh[64];
    __shared__ float smax[8];
    const float* x = (layer == 0) ? emb : (layer == 1 ? g_x1 : g_x2);
    int tid = threadIdx.x;
    int rb = blockIdx.x * 128;

    const float4* Wg4 = (const float4*)W;
#pragma unroll
    for (int idx = tid; idx < 1024; idx += 256) {
        int k = idx >> 4, n4 = (idx & 15) << 2;
        float4 w = Wg4[idx];
        Wn[n4 + 0][k] = __float2half(w.x);
        Wn[n4 + 1][k] = __float2half(w.y);
        Wn[n4 + 2][k] = __float2half(w.z);
        Wn[n4 + 3][k] = __float2half(w.w);
    }
    if (tid < 64) { ash[tid] = a_s[tid]; adh[tid] = a_d[tid]; }

    const float4* Xg4 = (const float4*)x;
#pragma unroll
    for (int idx = tid; idx < 2048; idx += 256) {
        int r = idx >> 4, c4 = (idx & 15) << 2;
        float4 v = (rb + r < NN) ? Xg4[(rb + r) * 16 + (idx & 15)]
                                 : make_float4(0.f, 0.f, 0.f, 0.f);
        __half2* dst = (__half2*)&Xh[r][c4];
        dst[0] = __float22half2_rn(make_float2(v.x, v.y));
        dst[1] = __float22half2_rn(make_float2(v.z, v.w));
    }
    __syncthreads();

    int warp = tid >> 5, lane = tid & 31;
    int gid = lane >> 2, tig = lane & 3;

    // ldmatrix base addresses
    // A: tiles (r0-7,k0-7)(r8-15,k0-7)(r0-7,k8-15)(r8-15,k8-15)
    unsigned abase = sptr(&Xh[warp * 16 + (lane & 15)][(lane & 16) ? 8 : 0]);
    // B pair p: tiles (n=p16+0-7,klo)(same,khi)(n=p16+8-15,klo)(same,khi)
    unsigned bbase[4];
#pragma unroll
    for (int p = 0; p < 4; p++)
        bbase[p] = sptr(&Wn[p * 16 + ((lane & 16) >> 1) + (lane & 7)]
                          [(lane & 8) ? 8 : 0]);

    float acc[8][4];
#pragma unroll
    for (int nt = 0; nt < 8; nt++)
#pragma unroll
        for (int j = 0; j < 4; j++) acc[nt][j] = 0.f;

#pragma unroll
    for (int ks = 0; ks < 4; ks++) {
        unsigned kb2 = ks * 32;   // bytes: 16 halfs per k-step
        unsigned a0, a1, a2, a3;
        ldsm4(a0, a1, a2, a3, abase + kb2);
#pragma unroll
        for (int p = 0; p < 4; p++) {
            unsigned b0, b1, b2, b3;
            ldsm4(b0, b1, b2, b3, bbase[p] + kb2);
            mma16816(acc[2 * p][0], acc[2 * p][1], acc[2 * p][2], acc[2 * p][3],
                     a0, a1, a2, a3, b0, b1);
            mma16816(acc[2 * p + 1][0], acc[2 * p + 1][1], acc[2 * p + 1][2], acc[2 * p + 1][3],
                     a0, a1, a2, a3, b2, b3);
        }
    }

    // store h fp16 + es/ed partial dots
    int grow0 = rb + warp * 16 + gid;
    int grow8 = grow0 + 8;
    float ps0 = 0.f, pd0 = 0.f, ps8 = 0.f, pd8 = 0.f;
#pragma unroll
    for (int nt = 0; nt < 8; nt++) {
        int col = nt * 8 + 2 * tig;
        if (grow0 < NN)
            *(__half2*)&g_h16[grow0 * 64 + col] =
                __float22half2_rn(make_float2(acc[nt][0], acc[nt][1]));
        if (grow8 < NN)
            *(__half2*)&g_h16[grow8 * 64 + col] =
                __float22half2_rn(make_float2(acc[nt][2], acc[nt][3]));
        float s0 = ash[col], s1 = ash[col + 1];
        float d0 = adh[col], d1 = adh[col + 1];
        ps0 += acc[nt][0] * s0 + acc[nt][1] * s1;
        pd0 += acc[nt][0] * d0 + acc[nt][1] * d1;
        ps8 += acc[nt][2] * s0 + acc[nt][3] * s1;
        pd8 += acc[nt][2] * d0 + acc[nt][3] * d1;
    }
    ps0 += __shfl_xor_sync(0xffffffffu, ps0, 1);
    ps0 += __shfl_xor_sync(0xffffffffu, ps0, 2);
    pd0 += __shfl_xor_sync(0xffffffffu, pd0, 1);
    pd0 += __shfl_xor_sync(0xffffffffu, pd0, 2);
    ps8 += __shfl_xor_sync(0xffffffffu, ps8, 1);
    ps8 += __shfl_xor_sync(0xffffffffu, ps8, 2);
    pd8 += __shfl_xor_sync(0xffffffffu, pd8, 1);
    pd8 += __shfl_xor_sync(0xffffffffu, pd8, 2);
    if (tig == 0) {
        if (grow0 < NN) { g_es[grow0] = ps0; g_ed[grow0] = pd0; }
        if (grow8 < NN) { g_es[grow8] = ps8; g_ed[grow8] = pd8; }
    }

    float mmax = -3.4e38f;
    if (grow0 < NN) mmax = fmaxf(mmax, ps0);
    if (grow8 < NN) mmax = fmaxf(mmax, ps8);
#pragma unroll
    for (int o = 16; o > 0; o >>= 1)
        mmax = fmaxf(mmax, __shfl_xor_sync(0xffffffffu, mmax, o));
    if (lane == 0) smax[warp] = mmax;
    __syncthreads();
    if (tid == 0) {
        float bm = smax[0];
#pragma unroll
        for (int j = 1; j < 8; j++) bm = fmaxf(bm, smax[j]);
        atomicMax(&g_gmaxu[layer], fenc(bm));
    }
}

// ---- per-edge softmax numerators (edge-parallel, no redundancy) ----
__global__ void __launch_bounds__(256) k_weight(int layer) {
    int i = blockIdx.x * blockDim.x + threadIdx.x;
    if (i >= ETOT) return;
    float gmax = fdec(g_gmaxu[layer]);
    int2 cd = __ldg(&g_csrd[i]);
    float edd = __ldg(&g_ed[cd.y]);
    float e = __ldg(&g_es[cd.x]) + edd;
    e = (e > 0.f) ? e : 0.2f * e;
    float gm = gmax + edd;
    float m = (gm > 0.f) ? gm : 0.2f * gm;   // >= segment max (lrelu monotone)
    g_w[i] = __expf(e - m);
}

// ---- aggregate: warp per node, 2 half-warps, precomputed weights ----
__global__ void __launch_bounds__(256) k_agg(
    int layer, const float* __restrict__ bias,
    const float4* __restrict__ emb4, float4* __restrict__ out4)
{
    __shared__ float sbias[64];
    int tid = threadIdx.x;
    if (tid < 64) sbias[tid] = bias[tid];
    __syncthreads();

    int lane = tid & 31;
    int n = blockIdx.x * 8 + (tid >> 5);
    if (n >= NN) return;

    int beg = g_rowptr[n];
    int end = g_rowptr[n + 1];

    int half = lane >> 4, hl = lane & 15;
    float denom = 0.f;
    float4 acc = make_float4(0.f, 0.f, 0.f, 0.f);
    const uint2* h2 = (const uint2*)g_h16;
    const int* csr = (const int*)g_csrd;   // .x at index 2k

#pragma unroll 4
    for (int k = beg + half; k < end; k += 2) {
        int s = __ldg(&csr[2 * k]);
        float w = __ldg(&g_w[k]);
        denom += w;
        uint2 hv = h2[s * 16 + hl];
        float2 lo = __half22float2(*(__half2*)&hv.x);
        float2 hi = __half22float2(*(__half2*)&hv.y);
        acc.x = fmaf(w, lo.x, acc.x);
        acc.y = fmaf(w, lo.y, acc.y);
        acc.z = fmaf(w, hi.x, acc.z);
        acc.w = fmaf(w, hi.y, acc.w);
    }
    denom += __shfl_xor_sync(0xffffffffu, denom, 16);
    acc.x += __shfl_xor_sync(0xffffffffu, acc.x, 16);
    acc.y += __shfl_xor_sync(0xffffffffu, acc.y, 16);
    acc.z += __shfl_xor_sync(0xffffffffu, acc.z, 16);
    acc.w += __shfl_xor_sync(0xffffffffu, acc.w, 16);

    if (half == 0) {
        float inv = 1.f / (denom + 1e-16f);
        float4 b4 = ((const float4*)sbias)[hl];
        float4 v;
        v.x = acc.x * inv + b4.x;
        v.y = acc.y * inv + b4.y;
        v.z = acc.z * inv + b4.z;
        v.w = acc.w * inv + b4.w;
        v.x = (v.x > 0.f) ? v.x : expm1f(v.x);
        v.y = (v.y > 0.f) ? v.y : expm1f(v.y);
        v.z = (v.z > 0.f) ? v.z : expm1f(v.z);
        v.w = (v.w > 0.f) ? v.w : expm1f(v.w);

        int base = n * 16 + hl;
        if (layer == 2) {
            float4 e4 = emb4[base];
            float4 a4 = ((const float4*)g_x1)[base];
            float4 c4 = ((const float4*)g_x2)[base];
            float4 o4;
            o4.x = (e4.x + a4.x + c4.x + v.x) * 0.25f;
            o4.y = (e4.y + a4.y + c4.y + v.y) * 0.25f;
            o4.z = (e4.z + a4.z + c4.z + v.z) * 0.25f;
            o4.w = (e4.w + a4.w + c4.w + v.w) * 0.25f;
            out4[base] = o4;
        } else {
            float4* xo = (float4*)((layer == 0) ? g_x1 : g_x2);
            xo[base] = v;
        }
    }
}

extern "C" void kernel_launch(void* const* d_in, const int* in_sizes, int n_in,
                              void* d_out, int out_size) {
    const int*   ei   = (const int*)d_in[0];
    const float* emb  = (const float*)d_in[1];
    const float* W    = (const float*)d_in[2];
    const float* a_s  = (const float*)d_in[3];
    const float* a_d  = (const float*)d_in[4];
    const float* bias = (const float*)d_in[5];
    float* out = (float*)d_out;

    const int* srcs = ei;
    const int* dsts = ei + EE;

    k_initsmall<<<(NN + 255) / 256, 256>>>();
    k_count<<<(EE / 4 + 255) / 256, 256>>>(dsts);
    k_bsum<<<NB_SCAN, 256>>>();
    // transform(l0): no CSR dependency, 4th slot so ncu profiles it
    k_transform<<<(NN + 127) / 128, 256>>>(0, emb, W, a_s, a_d);
    k_fillptr<<<NB_SCAN, 256>>>();
    k_fill<<<(ETOT + 255) / 256, 256>>>(srcs, dsts);
    k_weight<<<(ETOT + 255) / 256, 256>>>(0);
    k_agg<<<(NN + 7) / 8, 256>>>(0, bias, (const float4*)emb, (float4*)out);

    for (int l = 1; l < 3; l++) {
        k_transform<<<(NN + 127) / 128, 256>>>(l, emb, W + l * DD * DD,
                                               a_s + l * DD, a_d + l * DD);
        k_weight<<<(ETOT + 255) / 256, 256>>>(l);
        k_agg<<<(NN + 7) / 8, 256>>>(l, bias + l * DD, (const float4*)emb, (float4*)out);
    }
}